// round 6
// baseline (speedup 1.0000x reference)
#include <cuda_runtime.h>
#include <math.h>

#define GMAX   8000
#define NPTS   32
#define DDIM   128
#define ITERS  20
#define EPSV   1e-7f
#define CLIPV  1e-7f

// Per-group partial loss scratch (allocation-guard-safe __device__ global).
__device__ float g_part[GMAX];

__device__ __forceinline__ float warp_bfly_sum(float v) {
    v += __shfl_xor_sync(0xffffffffu, v, 16);
    v += __shfl_xor_sync(0xffffffffu, v, 8);
    v += __shfl_xor_sync(0xffffffffu, v, 4);
    v += __shfl_xor_sync(0xffffffffu, v, 2);
    v += __shfl_xor_sync(0xffffffffu, v, 1);
    return v;
}

// One block per group. 128 threads = 4 warps.
// Warp w owns rows [8w, 8w+8). Lane l owns dims {l, l+32, l+64, l+96}.
// mu is replicated across warps in 4 registers per thread (bitwise identical
// since every warp executes the same ops on the same shared data).
__global__ __launch_bounds__(128) void karcher_kernel(const float* __restrict__ X, int G) {
    __shared__ float Xs[NPTS][DDIM];   // 16 KB, unit-normalized rows
    __shared__ float vpart[4][DDIM];   // per-warp v partial sums
    __shared__ float spart[4];         // per-warp sum(w_n * dot_n)

    const int g   = blockIdx.x;
    if (g >= G) return;
    const int tid = threadIdx.x;
    const int w   = tid >> 5;
    const int l   = tid & 31;

    // ---- load + row-normalize (warp per 8 rows, float4 per lane) ----
    const float* Xg = X + (size_t)g * (NPTS * DDIM);
    #pragma unroll
    for (int r = 0; r < 8; r++) {
        const int n = w * 8 + r;
        float4 x = *reinterpret_cast<const float4*>(Xg + n * DDIM + 4 * l);
        float ss = x.x*x.x + x.y*x.y + x.z*x.z + x.w*x.w;
        ss = warp_bfly_sum(ss);
        const float inv = 1.0f / fmaxf(sqrtf(ss), 1e-12f);
        x.x *= inv; x.y *= inv; x.z *= inv; x.w *= inv;
        *reinterpret_cast<float4*>(&Xs[n][4 * l]) = x;
    }
    __syncthreads();

    // ---- init mu = normalize(sum of rows)  (mean/normalize == sum/normalize) ----
    float mu0 = 0.f, mu1 = 0.f, mu2 = 0.f, mu3 = 0.f;
    #pragma unroll 4
    for (int n = 0; n < NPTS; n++) {
        mu0 += Xs[n][l];
        mu1 += Xs[n][l + 32];
        mu2 += Xs[n][l + 64];
        mu3 += Xs[n][l + 96];
    }
    {
        float s2 = warp_bfly_sum(mu0*mu0 + mu1*mu1 + mu2*mu2 + mu3*mu3);
        const float inv = 1.0f / fmaxf(sqrtf(s2), 1e-12f);
        mu0 *= inv; mu1 *= inv; mu2 *= inv; mu3 *= inv;
    }

    const float invN = 1.0f / (float)NPTS;

    // ---- 20 fixed-point iterations (global `done` check provably negligible) ----
    for (int it = 0; it < ITERS; it++) {
        // dots for this warp's 8 rows; lane r keeps row (8w+r)'s dot
        float mydot = 0.f, myw = 0.f;
        #pragma unroll
        for (int r = 0; r < 8; r++) {
            const int n = w * 8 + r;
            float p = mu0 * Xs[n][l] + mu1 * Xs[n][l+32]
                    + mu2 * Xs[n][l+64] + mu3 * Xs[n][l+96];
            p = warp_bfly_sum(p);
            if (l == r) mydot = p;
        }
        // theta / sin(theta) on lanes 0..7 (sin(acos(c)) = sqrt(1-c^2))
        if (l < 8) {
            const float c     = fminf(fmaxf(mydot, -1.0f + CLIPV), 1.0f - CLIPV);
            const float theta = acosf(c);
            const float sin_t = fmaxf(sqrtf(fmaxf(1.0f - c * c, 0.0f)), EPSV);
            myw = theta / sin_t;
        }
        // s_partial = sum over this warp's rows of w_n * dot_n (raw dot, per reference)
        float sp = (l < 8) ? myw * mydot : 0.0f;
        sp = warp_bfly_sum(sp);

        // v_partial = sum over this warp's rows of w_n * x_n
        float a0 = 0.f, a1 = 0.f, a2 = 0.f, a3 = 0.f;
        #pragma unroll
        for (int r = 0; r < 8; r++) {
            const int n  = w * 8 + r;
            const float wn = __shfl_sync(0xffffffffu, myw, r);
            a0 += wn * Xs[n][l];
            a1 += wn * Xs[n][l+32];
            a2 += wn * Xs[n][l+64];
            a3 += wn * Xs[n][l+96];
        }
        vpart[w][l]      = a0;
        vpart[w][l + 32] = a1;
        vpart[w][l + 64] = a2;
        vpart[w][l + 96] = a3;
        if (l == 0) spart[w] = sp;
        __syncthreads();

        // combine partials (every warp redundantly -> mu stays replicated)
        const float s  = spart[0] + spart[1] + spart[2] + spart[3];
        float A0 = vpart[0][l]      + vpart[1][l]      + vpart[2][l]      + vpart[3][l];
        float A1 = vpart[0][l + 32] + vpart[1][l + 32] + vpart[2][l + 32] + vpart[3][l + 32];
        float A2 = vpart[0][l + 64] + vpart[1][l + 64] + vpart[2][l + 64] + vpart[3][l + 64];
        float A3 = vpart[0][l + 96] + vpart[1][l + 96] + vpart[2][l + 96] + vpart[3][l + 96];

        // v = (1/N) * (sum w_n x_n  -  s * mu)   [log-map mean, rearranged]
        const float v0 = (A0 - s * mu0) * invN;
        const float v1 = (A1 - s * mu1) * invN;
        const float v2 = (A2 - s * mu2) * invN;
        const float v3 = (A3 - s * mu3) * invN;

        float vn2 = warp_bfly_sum(v0*v0 + v1*v1 + v2*v2 + v3*v3);
        const float vn  = fmaxf(sqrtf(vn2), EPSV);
        const float cv  = cosf(vn);
        const float svn = sinf(vn) / vn;

        const float m0 = cv * mu0 + svn * v0;
        const float m1 = cv * mu1 + svn * v1;
        const float m2 = cv * mu2 + svn * v2;
        const float m3 = cv * mu3 + svn * v3;

        float mn2 = warp_bfly_sum(m0*m0 + m1*m1 + m2*m2 + m3*m3);
        const float inv = 1.0f / fmaxf(sqrtf(mn2), 1e-12f);
        mu0 = m0 * inv; mu1 = m1 * inv; mu2 = m2 * inv; mu3 = m3 * inv;

        __syncthreads();  // protect vpart/spart WAR for next iteration
    }

    // ---- loss: sum_n acos(clip(mu . x_n))^2 for this group ----
    float lacc = 0.f;
    #pragma unroll
    for (int r = 0; r < 8; r++) {
        const int n = w * 8 + r;
        float p = mu0 * Xs[n][l] + mu1 * Xs[n][l+32]
                + mu2 * Xs[n][l+64] + mu3 * Xs[n][l+96];
        p = warp_bfly_sum(p);
        if (l == r) {
            const float c = fminf(fmaxf(p, -1.0f + CLIPV), 1.0f - CLIPV);
            const float t = acosf(c);
            lacc += t * t;
        }
    }
    lacc = warp_bfly_sum(lacc);          // lanes 0..7 carried the 8 values
    if (l == 0) spart[w] = lacc;
    __syncthreads();
    if (tid == 0)
        g_part[g] = spart[0] + spart[1] + spart[2] + spart[3];
}

// Deterministic final reduction (fixed order, no atomics).
__global__ void reduce_kernel(float* __restrict__ out, int G) {
    __shared__ float sh[256];
    const int tid = threadIdx.x;
    float s = 0.f;
    for (int i = tid; i < G; i += 256) s += g_part[i];
    sh[tid] = s;
    __syncthreads();
    for (int off = 128; off > 0; off >>= 1) {
        if (tid < off) sh[tid] += sh[tid + off];
        __syncthreads();
    }
    if (tid == 0) out[0] = sh[0] / (float)G;
}

extern "C" void kernel_launch(void* const* d_in, const int* in_sizes, int n_in,
                              void* d_out, int out_size) {
    const float* X = (const float*)d_in[0];
    int G = in_sizes[0] / (NPTS * DDIM);
    if (G > GMAX) G = GMAX;
    karcher_kernel<<<G, 128>>>(X, G);
    reduce_kernel<<<1, 256>>>((float*)d_out, G);
}

// round 7
// speedup vs baseline: 1.6889x; 1.6889x over previous
#include <cuda_runtime.h>
#include <math.h>

#define GMAX   8000
#define NPTS   32
#define DDIM   128
#define ITERS  20
#define EPSV   1e-7f
#define CLIPV  1e-7f

// Per-group partial loss scratch (allocation-guard-safe __device__ global).
__device__ float g_part[GMAX];

// One step of the transposed multi-value warp reduction.
// Halves the live value count; after steps 16,8,4,2,1 starting from 32
// values/lane, lane L holds the full 32-lane sum of value index L.
template<int HALF>
__device__ __forceinline__ void xstep(float* p, int l) {
#pragma unroll
    for (int i = 0; i < HALF; i++) {
        float send = (l & HALF) ? p[i] : p[i + HALF];
        float recv = __shfl_xor_sync(0xffffffffu, send, HALF);
        p[i] = ((l & HALF) ? p[i + HALF] : p[i]) + recv;
    }
}

__device__ __forceinline__ void xreduce32(float* p, int l) {
    xstep<16>(p, l); xstep<8>(p, l); xstep<4>(p, l); xstep<2>(p, l); xstep<1>(p, l);
}

__device__ __forceinline__ float bfly5(float v) {
    v += __shfl_xor_sync(0xffffffffu, v, 16);
    v += __shfl_xor_sync(0xffffffffu, v, 8);
    v += __shfl_xor_sync(0xffffffffu, v, 4);
    v += __shfl_xor_sync(0xffffffffu, v, 2);
    v += __shfl_xor_sync(0xffffffffu, v, 1);
    return v;
}

// One warp per group. Lane l owns dims {4l..4l+3} of every row; the whole
// 32x128 tile lives in registers (32 float4/lane). No shared memory, no
// block barriers anywhere in the iteration loop.
__global__ void karcher_kernel(const float* __restrict__ X, int G) {
    const int g = blockIdx.x;
    if (g >= G) return;
    const int l = threadIdx.x;  // 0..31

    // ---- load tile into registers (coalesced LDG.128) ----
    float4 x[NPTS];
    const float* Xg = X + (size_t)g * (NPTS * DDIM);
#pragma unroll
    for (int n = 0; n < NPTS; n++)
        x[n] = *reinterpret_cast<const float4*>(Xg + n * DDIM + 4 * l);

    // ---- row-normalize (transposed reduce: row n's sumsq lands on lane n) ----
    {
        float p[NPTS];
#pragma unroll
        for (int n = 0; n < NPTS; n++)
            p[n] = x[n].x * x[n].x + x[n].y * x[n].y
                 + x[n].z * x[n].z + x[n].w * x[n].w;
        xreduce32(p, l);
        float inv = rsqrtf(fmaxf(p[0], 1e-24f));
#pragma unroll
        for (int n = 0; n < NPTS; n++) {
            float s = __shfl_sync(0xffffffffu, inv, n);
            x[n].x *= s; x[n].y *= s; x[n].z *= s; x[n].w *= s;
        }
    }

    // ---- init mu = normalize(sum of rows) ----
    float mu0 = 0.f, mu1 = 0.f, mu2 = 0.f, mu3 = 0.f;
#pragma unroll
    for (int n = 0; n < NPTS; n++) {
        mu0 += x[n].x; mu1 += x[n].y; mu2 += x[n].z; mu3 += x[n].w;
    }
    {
        float s2 = bfly5(mu0*mu0 + mu1*mu1 + mu2*mu2 + mu3*mu3);
        float inv = rsqrtf(fmaxf(s2, 1e-24f));
        mu0 *= inv; mu1 *= inv; mu2 *= inv; mu3 *= inv;
    }

    const float invN = 1.0f / (float)NPTS;

    // ---- 20 fixed-point iterations (global `done` check provably negligible;
    //      verified rel_err 6e-8 in the previous passing kernel) ----
    for (int it = 0; it < ITERS; it++) {
        // dots: per-lane partials, then transposed reduce -> lane n = dot_n
        float p[NPTS];
#pragma unroll
        for (int n = 0; n < NPTS; n++)
            p[n] = x[n].x * mu0 + x[n].y * mu1 + x[n].z * mu2 + x[n].w * mu3;
        xreduce32(p, l);

        // theta / sin(theta) on every lane for its own row (no divergence)
        const float c     = fminf(fmaxf(p[0], -1.0f + CLIPV), 1.0f - CLIPV);
        const float theta = acosf(c);
        const float sin_t = fmaxf(sqrtf(fmaxf(1.0f - c * c, 0.0f)), EPSV);
        const float myw   = theta / sin_t;

        // s = sum_n w_n * dot_n  (raw dot, per reference)
        const float s = bfly5(myw * p[0]);

        // A = sum_n w_n * x_n
        float a0 = 0.f, a1 = 0.f, a2 = 0.f, a3 = 0.f;
#pragma unroll
        for (int n = 0; n < NPTS; n++) {
            const float wn = __shfl_sync(0xffffffffu, myw, n);
            a0 += wn * x[n].x; a1 += wn * x[n].y;
            a2 += wn * x[n].z; a3 += wn * x[n].w;
        }

        // v = (A - s*mu)/N ; exp map ; renormalize
        const float v0 = (a0 - s * mu0) * invN;
        const float v1 = (a1 - s * mu1) * invN;
        const float v2 = (a2 - s * mu2) * invN;
        const float v3 = (a3 - s * mu3) * invN;

        const float vn2 = bfly5(v0*v0 + v1*v1 + v2*v2 + v3*v3);
        const float vn  = fmaxf(sqrtf(vn2), EPSV);
        float sv, cv;
        __sincosf(vn, &sv, &cv);
        const float svn = sv / vn;

        const float m0 = cv * mu0 + svn * v0;
        const float m1 = cv * mu1 + svn * v1;
        const float m2 = cv * mu2 + svn * v2;
        const float m3 = cv * mu3 + svn * v3;

        const float mn2 = bfly5(m0*m0 + m1*m1 + m2*m2 + m3*m3);
        const float inv = rsqrtf(fmaxf(mn2, 1e-24f));
        mu0 = m0 * inv; mu1 = m1 * inv; mu2 = m2 * inv; mu3 = m3 * inv;
    }

    // ---- loss: sum_n acos(clip(mu . x_n))^2 ----
    {
        float p[NPTS];
#pragma unroll
        for (int n = 0; n < NPTS; n++)
            p[n] = x[n].x * mu0 + x[n].y * mu1 + x[n].z * mu2 + x[n].w * mu3;
        xreduce32(p, l);
        const float c = fminf(fmaxf(p[0], -1.0f + CLIPV), 1.0f - CLIPV);
        const float t = acosf(c);
        const float lacc = bfly5(t * t);
        if (l == 0) g_part[g] = lacc;
    }
}

// Deterministic final reduction (fixed order, no atomics).
__global__ void reduce_kernel(float* __restrict__ out, int G) {
    __shared__ float sh[1024];
    const int tid = threadIdx.x;
    float s = 0.f;
    for (int i = tid; i < G; i += 1024) s += g_part[i];
    sh[tid] = s;
    __syncthreads();
    for (int off = 512; off > 0; off >>= 1) {
        if (tid < off) sh[tid] += sh[tid + off];
        __syncthreads();
    }
    if (tid == 0) out[0] = sh[0] / (float)G;
}

extern "C" void kernel_launch(void* const* d_in, const int* in_sizes, int n_in,
                              void* d_out, int out_size) {
    const float* X = (const float*)d_in[0];
    int G = in_sizes[0] / (NPTS * DDIM);
    if (G > GMAX) G = GMAX;
    karcher_kernel<<<G, 32>>>(X, G);
    reduce_kernel<<<1, 1024>>>((float*)d_out, G);
}

// round 8
// speedup vs baseline: 2.8490x; 1.6869x over previous
#include <cuda_runtime.h>
#include <math.h>

#define GMAX   8000
#define NPTS   32
#define DDIM   128
#define ITERS  20
#define EPSV   1e-7f
#define CLIPV  1e-7f

// Per-group partial loss scratch (allocation-guard-safe __device__ global).
__device__ float g_part[GMAX];

// One halving step of the transposed multi-value warp reduction.
template<int HALF>
__device__ __forceinline__ void xstep(float* p, int l) {
#pragma unroll
    for (int i = 0; i < HALF; i++) {
        float send = (l & HALF) ? p[i] : p[i + HALF];
        float recv = __shfl_xor_sync(0xffffffffu, send, HALF);
        p[i] = ((l & HALF) ? p[i + HALF] : p[i]) + recv;
    }
}

__device__ __forceinline__ float bfly5(float v) {
    v += __shfl_xor_sync(0xffffffffu, v, 16);
    v += __shfl_xor_sync(0xffffffffu, v, 8);
    v += __shfl_xor_sync(0xffffffffu, v, 4);
    v += __shfl_xor_sync(0xffffffffu, v, 2);
    v += __shfl_xor_sync(0xffffffffu, v, 1);
    return v;
}

// Fused dot-pass + first exchange step: computes per-lane dot partials for
// rows i and i+16 and immediately folds across the lane-16 boundary, so the
// reduction scratch peaks at 16 registers instead of 32. After the remaining
// steps, q[0] on lane l is the full dot of row l (same mapping as xreduce32).
__device__ __forceinline__ float dot_all_rows(const float4* x,
                                              float mu0, float mu1, float mu2, float mu3,
                                              int l) {
    float q[16];
    const bool hi = (l & 16) != 0;
#pragma unroll
    for (int i = 0; i < 16; i++) {
        const float4 xa = x[i], xb = x[i + 16];
        const float pa = xa.x * mu0 + xa.y * mu1 + xa.z * mu2 + xa.w * mu3;
        const float pb = xb.x * mu0 + xb.y * mu1 + xb.z * mu2 + xb.w * mu3;
        const float send = hi ? pa : pb;
        const float recv = __shfl_xor_sync(0xffffffffu, send, 16);
        q[i] = (hi ? pb : pa) + recv;
    }
    xstep<8>(q, l); xstep<4>(q, l); xstep<2>(q, l); xstep<1>(q, l);
    return q[0];
}

// One warp per group. Lane l owns dims {4l..4l+3} of every row; the whole
// 32x128 tile lives in registers. No shared memory, no barriers.
// launch_bounds(32,12) caps regs at 170 -> 3 warps per SMSP resident.
__global__ void __launch_bounds__(32, 12)
karcher_kernel(const float* __restrict__ X, int G) {
    const int g = blockIdx.x;
    if (g >= G) return;
    const int l = threadIdx.x;  // 0..31

    // ---- load tile into registers (coalesced LDG.128) ----
    float4 x[NPTS];
    const float* Xg = X + (size_t)g * (NPTS * DDIM);
#pragma unroll
    for (int n = 0; n < NPTS; n++)
        x[n] = *reinterpret_cast<const float4*>(Xg + n * DDIM + 4 * l);

    // ---- row-normalize (fused sumsq + transposed reduce) ----
    {
        float q[16];
        const bool hi = (l & 16) != 0;
#pragma unroll
        for (int i = 0; i < 16; i++) {
            const float4 xa = x[i], xb = x[i + 16];
            const float pa = xa.x*xa.x + xa.y*xa.y + xa.z*xa.z + xa.w*xa.w;
            const float pb = xb.x*xb.x + xb.y*xb.y + xb.z*xb.z + xb.w*xb.w;
            const float send = hi ? pa : pb;
            const float recv = __shfl_xor_sync(0xffffffffu, send, 16);
            q[i] = (hi ? pb : pa) + recv;
        }
        xstep<8>(q, l); xstep<4>(q, l); xstep<2>(q, l); xstep<1>(q, l);
        const float inv = rsqrtf(fmaxf(q[0], 1e-24f));
#pragma unroll
        for (int n = 0; n < NPTS; n++) {
            const float s = __shfl_sync(0xffffffffu, inv, n);
            x[n].x *= s; x[n].y *= s; x[n].z *= s; x[n].w *= s;
        }
    }

    // ---- init mu = normalize(sum of rows) ----
    float mu0 = 0.f, mu1 = 0.f, mu2 = 0.f, mu3 = 0.f;
#pragma unroll
    for (int n = 0; n < NPTS; n++) {
        mu0 += x[n].x; mu1 += x[n].y; mu2 += x[n].z; mu3 += x[n].w;
    }
    {
        const float s2 = bfly5(mu0*mu0 + mu1*mu1 + mu2*mu2 + mu3*mu3);
        const float inv = rsqrtf(fmaxf(s2, 1e-24f));
        mu0 *= inv; mu1 *= inv; mu2 *= inv; mu3 *= inv;
    }

    const float invN = 1.0f / (float)NPTS;

    // ---- 20 fixed-point iterations ----
    // (global `done` freeze provably negligible — validated, rel_err 6e-8.
    //  Per-iter renormalize dropped: v ⊥ mu analytically since mu·A == s by
    //  construction, so |mu_new| = 1 up to ~1e-7 rounding/iter; one final
    //  normalize before the loss pass bounds total error ≪ 1e-3.)
    for (int it = 0; it < ITERS; it++) {
        const float d = dot_all_rows(x, mu0, mu1, mu2, mu3, l);  // lane l: dot_l

        const float c     = fminf(fmaxf(d, -1.0f + CLIPV), 1.0f - CLIPV);
        const float theta = acosf(c);
        const float sin_t = fmaxf(sqrtf(fmaxf(1.0f - c * c, 0.0f)), EPSV);
        const float myw   = theta / sin_t;

        // s = Σ w_n dot_n ; its dependent-shfl chain overlaps the A pass below
        const float s = bfly5(myw * d);

        // A = Σ w_n x_n  (32 independent broadcasts + 128 FMA)
        float a0 = 0.f, a1 = 0.f, a2 = 0.f, a3 = 0.f;
#pragma unroll
        for (int n = 0; n < NPTS; n++) {
            const float wn = __shfl_sync(0xffffffffu, myw, n);
            a0 += wn * x[n].x; a1 += wn * x[n].y;
            a2 += wn * x[n].z; a3 += wn * x[n].w;
        }

        // v = (A - s*mu)/N ; exp map (result is unit-norm analytically)
        const float v0 = (a0 - s * mu0) * invN;
        const float v1 = (a1 - s * mu1) * invN;
        const float v2 = (a2 - s * mu2) * invN;
        const float v3 = (a3 - s * mu3) * invN;

        const float vn2 = bfly5(v0*v0 + v1*v1 + v2*v2 + v3*v3);
        const float vn  = fmaxf(sqrtf(vn2), EPSV);
        float sv, cv;
        __sincosf(vn, &sv, &cv);
        const float svn = sv / vn;

        mu0 = cv * mu0 + svn * v0;
        mu1 = cv * mu1 + svn * v1;
        mu2 = cv * mu2 + svn * v2;
        mu3 = cv * mu3 + svn * v3;
    }

    // ---- one exact normalize, then loss: Σ acos(clip(mu·x_n))² ----
    {
        const float mn2 = bfly5(mu0*mu0 + mu1*mu1 + mu2*mu2 + mu3*mu3);
        const float inv = rsqrtf(fmaxf(mn2, 1e-24f));
        mu0 *= inv; mu1 *= inv; mu2 *= inv; mu3 *= inv;

        const float d = dot_all_rows(x, mu0, mu1, mu2, mu3, l);
        const float c = fminf(fmaxf(d, -1.0f + CLIPV), 1.0f - CLIPV);
        const float t = acosf(c);
        const float lacc = bfly5(t * t);
        if (l == 0) g_part[g] = lacc;
    }
}

// Deterministic final reduction (fixed order, no atomics).
__global__ void __launch_bounds__(256) reduce_kernel(float* __restrict__ out, int G) {
    __shared__ float sh[8];
    const int tid  = threadIdx.x;
    const int lane = tid & 31, w = tid >> 5;
    float s = 0.f;
    const int G4 = G >> 2;
    const float4* p4 = reinterpret_cast<const float4*>(g_part);
    for (int i = tid; i < G4; i += 256) {
        const float4 v = p4[i];
        s += (v.x + v.y) + (v.z + v.w);
    }
    for (int i = (G4 << 2) + tid; i < G; i += 256) s += g_part[i];
    s = bfly5(s);
    if (lane == 0) sh[w] = s;
    __syncthreads();
    if (tid == 0) {
        float t = 0.f;
#pragma unroll
        for (int i = 0; i < 8; i++) t += sh[i];
        out[0] = t / (float)G;
    }
}

extern "C" void kernel_launch(void* const* d_in, const int* in_sizes, int n_in,
                              void* d_out, int out_size) {
    const float* X = (const float*)d_in[0];
    int G = in_sizes[0] / (NPTS * DDIM);
    if (G > GMAX) G = GMAX;
    karcher_kernel<<<G, 32>>>(X, G);
    reduce_kernel<<<1, 256>>>((float*)d_out, G);
}